// round 12
// baseline (speedup 1.0000x reference)
#include <cuda_runtime.h>
#include <math.h>

#define LVL 4
#define BAT 128
#define INW 512
#define CTXW 512
#define STW 512
#define RW 256
#define CW 256
#define DW 1536
#define KC 32
#define KHALF 768                     /* K per split-K block */
#define NCH (KHALF/KC)                /* 24 chunks per half */
#define H_SIZE (LVL*BAT*STW)          /* 262144 */
#define H_SIZE4 (H_SIZE/4)            /* 65536 */
#define M_LVL_STRIDE (BAT*RW*CW)      /* 8388608 */

// scratch (allocation-free rule: __device__ globals)
__device__ __align__(16) float g_gate_p[2][3][LVL][BAT][STW]; // split-K gate partials (6 MB)
__device__ __align__(16) float g_uv_p[2][2][LVL][BAT][RW];    // split-K u/v partials (2 MB)

__device__ __forceinline__ float sigmoidf_(float x) { return 1.0f / (1.0f + __expf(-x)); }

__device__ __forceinline__ void mma_tf32(float* d, unsigned a0, unsigned a1,
                                         unsigned a2, unsigned a3,
                                         unsigned b0, unsigned b1)
{
    asm volatile(
        "mma.sync.aligned.m16n8k8.row.col.f32.tf32.tf32.f32 "
        "{%0,%1,%2,%3}, {%4,%5,%6,%7}, {%8,%9}, {%0,%1,%2,%3};\n"
        : "+f"(d[0]), "+f"(d[1]), "+f"(d[2]), "+f"(d[3])
        : "r"(a0), "r"(a1), "r"(a2), "r"(a3), "r"(b0), "r"(b1));
}

__device__ __forceinline__ void cp16(void* dst, const void* src) {
    unsigned ds = (unsigned)__cvta_generic_to_shared(dst);
    asm volatile("cp.async.ca.shared.global [%0], [%1], 16;" :: "r"(ds), "l"(src));
}
__device__ __forceinline__ void cp_commit() { asm volatile("cp.async.commit_group;"); }
template<int N> __device__ __forceinline__ void cp_wait() {
    asm volatile("cp.async.wait_group %0;" :: "n"(N));
}

// ===========================================================================
// 3-stage pipelined tf32 GEMM core over K range [KBASE, KBASE+KHALF).
// Tile M=64 x N=32, 128 threads (2x2 warps, warp tile 32x16).
// Stride-36 smem rows -> conflict-free fragment reads.
//
// TRUNCATION-MODE TF32: raw fp32 bits are fed to the tf32 MMA (HW reads only
// the top 19 bits) — removes 12 CVTs per warp k-step (43% of the hot loop).
//
// Pipeline: prologue issues stages 0,1; per iter: wait<1> (wait<0> on last
// iter — wait<1> with 1 pending group would not wait: R6-class bug),
// barrier, issue stage it+2 into slot (it+2)%3 (prior contents last read
// before this barrier), compute stage it%3.  R10/R11-proven.
// ===========================================================================
#define GEMM_PIPE_BODY(LOAD_A_PTR, LOAD_B_PTR, KBASE)                          \
    __shared__ float As[3][64][36];                                            \
    __shared__ float Bs[3][32][36];                                            \
    const int t = threadIdx.x;                                                 \
    const int w = t >> 5, lane = t & 31;                                       \
    const int wm = w >> 1, wn = w & 1;                                         \
    const int g = lane >> 2, tg = lane & 3;                                    \
    float acc[2][2][4];                                                        \
    _Pragma("unroll")                                                          \
    for (int mi = 0; mi < 2; mi++)                                             \
        _Pragma("unroll")                                                      \
        for (int ni = 0; ni < 2; ni++)                                         \
            _Pragma("unroll")                                                  \
            for (int r = 0; r < 4; r++) acc[mi][ni][r] = 0.0f;                 \
    auto load_chunk = [&](int kt, int s) {                                     \
        _Pragma("unroll")                                                      \
        for (int i = 0; i < 4; i++) {   /* A: 64x32 = 512 float4 */            \
            const int idx = i * 128 + t;                                       \
            const int row = idx >> 3, ch = idx & 7;                            \
            cp16(&As[s][row][ch * 4], LOAD_A_PTR(row, kt + ch * 4));           \
        }                                                                      \
        _Pragma("unroll")                                                      \
        for (int i = 0; i < 2; i++) {   /* B: 32x32 = 256 float4 */            \
            const int idx = i * 128 + t;                                       \
            const int row = idx >> 3, ch = idx & 7;                            \
            cp16(&Bs[s][row][ch * 4], LOAD_B_PTR(row, kt + ch * 4));           \
        }                                                                      \
        cp_commit();                                                           \
    };                                                                         \
    load_chunk(KBASE, 0);                                                      \
    load_chunk(KBASE + KC, 1);                                                 \
    for (int it = 0; it < NCH; ++it) {                                         \
        const int s = it % 3;                                                  \
        if (it + 1 < NCH) cp_wait<1>(); else cp_wait<0>();                     \
        __syncthreads();                                                       \
        if (it + 2 < NCH) load_chunk(KBASE + (it + 2) * KC, (it + 2) % 3);     \
        _Pragma("unroll")                                                      \
        for (int ks = 0; ks < 4; ks++) {                                       \
            const int k0 = ks * 8;                                             \
            unsigned a[2][4];                                                  \
            _Pragma("unroll")                                                  \
            for (int mi = 0; mi < 2; mi++) {                                   \
                const int r0 = wm * 32 + mi * 16;                              \
                a[mi][0] = __float_as_uint(As[s][r0 + g][k0 + tg]);            \
                a[mi][1] = __float_as_uint(As[s][r0 + g + 8][k0 + tg]);        \
                a[mi][2] = __float_as_uint(As[s][r0 + g][k0 + tg + 4]);        \
                a[mi][3] = __float_as_uint(As[s][r0 + g + 8][k0 + tg + 4]);    \
            }                                                                  \
            unsigned bb[2][2];                                                 \
            _Pragma("unroll")                                                  \
            for (int ni = 0; ni < 2; ni++) {                                   \
                const int n0 = wn * 16 + ni * 8 + g;                           \
                bb[ni][0] = __float_as_uint(Bs[s][n0][k0 + tg]);               \
                bb[ni][1] = __float_as_uint(Bs[s][n0][k0 + tg + 4]);           \
            }                                                                  \
            _Pragma("unroll")                                                  \
            for (int mi = 0; mi < 2; mi++)                                     \
                _Pragma("unroll")                                              \
                for (int ni = 0; ni < 2; ni++)                                 \
                    mma_tf32(acc[mi][ni], a[mi][0], a[mi][1], a[mi][2],        \
                             a[mi][3], bb[ni][0], bb[ni][1]);                  \
        }                                                                      \
    }

// ---------------------------------------------------------------------------
// Gate GEMM, split-K x2: g_gate_p[kh][gate][l][b][o] = partial dot (no bias).
// gi = x|c|h[l].  grid: (otile=16, y=mtile*2+kh=4, z=l*3+gate=12) = 768 blocks.
// ---------------------------------------------------------------------------
__global__ __launch_bounds__(128)
void gate_gemm(const float* __restrict__ x, const float* __restrict__ c,
               const float* __restrict__ h,
               const float* __restrict__ phi_w, const float* __restrict__ alpha_w,
               const float* __restrict__ beta_w)
{
    const int zz = blockIdx.z;
    const int l = zz / 3, gate = zz % 3;
    const int mtile = blockIdx.y >> 1;
    const int kh    = blockIdx.y & 1;
    const int otile = blockIdx.x;
    const int kbase = kh * KHALF;

    const float* W = (gate == 0 ? phi_w : gate == 1 ? alpha_w : beta_w) + (size_t)l * STW * DW;

    #define GA_PTR(row, k)                                                      \
        ((k) < INW ? x + (size_t)(mtile * 64 + (row)) * INW + (k)               \
         : (k) < INW + CTXW ? c + (size_t)(mtile * 64 + (row)) * CTXW + ((k) - INW) \
         : h + ((size_t)l * BAT + mtile * 64 + (row)) * STW + ((k) - INW - CTXW))
    #define GB_PTR(row, k)  (W + (size_t)(otile * 32 + (row)) * DW + (k))

    GEMM_PIPE_BODY(GA_PTR, GB_PTR, kbase)

    #undef GA_PTR
    #undef GB_PTR

    #pragma unroll
    for (int mi = 0; mi < 2; mi++) {
        const int r0 = mtile * 64 + wm * 32 + mi * 16;
        #pragma unroll
        for (int ni = 0; ni < 2; ni++) {
            const int o0 = otile * 32 + wn * 16 + ni * 8 + tg * 2;
            float2 v0 = { acc[mi][ni][0], acc[mi][ni][1] };
            float2 v1 = { acc[mi][ni][2], acc[mi][ni][3] };
            *(float2*)&g_gate_p[kh][gate][l][r0 + g][o0]     = v0;
            *(float2*)&g_gate_p[kh][gate][l][r0 + g + 8][o0] = v1;
        }
    }
}

// ---------------------------------------------------------------------------
// h_new = sigmoid(alpha)*tanh(phi) + sigmoid(beta)*h  -> d_out[0:H_SIZE]
// Sums the two split-K partials and adds biases.  float4 vectorized.
// Partials are L2-hot (6 MB, just written) -> default caching.
// ---------------------------------------------------------------------------
__global__ __launch_bounds__(256)
void hnew_kernel(const float* __restrict__ h,
                 const float* __restrict__ phi_b, const float* __restrict__ alpha_b,
                 const float* __restrict__ beta_b,
                 float* __restrict__ out)
{
    const int idx = blockIdx.x * blockDim.x + threadIdx.x;   // float4 index
    if (idx >= H_SIZE4) return;
    const float4* g0 = (const float4*)&g_gate_p[0][0][0][0][0];
    const float4* g1 = (const float4*)&g_gate_p[1][0][0][0][0];

    const int base = idx * 4;
    const int l = base >> 16;          // BAT*STW = 65536
    const int o = base & (STW - 1);
    const float4 pb = *(const float4*)(phi_b   + l * STW + o);
    const float4 ab = *(const float4*)(alpha_b + l * STW + o);
    const float4 bbv = *(const float4*)(beta_b + l * STW + o);

    float4 p0 = g0[idx],               p1 = g1[idx];
    float4 a0 = g0[H_SIZE4 + idx],     a1 = g1[H_SIZE4 + idx];
    float4 b0 = g0[2 * H_SIZE4 + idx], b1 = g1[2 * H_SIZE4 + idx];
    float4 hv = ((const float4*)h)[idx];

    float4 o4;
    o4.x = sigmoidf_(a0.x + a1.x + ab.x) * tanhf(p0.x + p1.x + pb.x) + sigmoidf_(b0.x + b1.x + bbv.x) * hv.x;
    o4.y = sigmoidf_(a0.y + a1.y + ab.y) * tanhf(p0.y + p1.y + pb.y) + sigmoidf_(b0.y + b1.y + bbv.y) * hv.y;
    o4.z = sigmoidf_(a0.z + a1.z + ab.z) * tanhf(p0.z + p1.z + pb.z) + sigmoidf_(b0.z + b1.z + bbv.z) * hv.z;
    o4.w = sigmoidf_(a0.w + a1.w + ab.w) * tanhf(p0.w + p1.w + pb.w) + sigmoidf_(b0.w + b1.w + bbv.w) * hv.w;
    ((float4*)out)[idx] = o4;
}

// ---------------------------------------------------------------------------
// u/v GEMM, split-K x2: g_uv_p[kh][which][l][b][r] = partial dot (no bias).
// wv = h_new|x|c.  grid: (otile=8, y=mtile*2+kh=4, z=l*2+which=8) = 256.
// ---------------------------------------------------------------------------
__global__ __launch_bounds__(128)
void uv_gemm(const float* __restrict__ hn, const float* __restrict__ x,
             const float* __restrict__ c,
             const float* __restrict__ u_w, const float* __restrict__ v_w)
{
    const int zz = blockIdx.z;
    const int l = zz >> 1, which = zz & 1;
    const int mtile = blockIdx.y >> 1;
    const int kh    = blockIdx.y & 1;
    const int otile = blockIdx.x;
    const int kbase = kh * KHALF;

    const float* W = (which ? v_w : u_w) + (size_t)l * RW * DW;

    #define UA_PTR(row, k)                                                      \
        ((k) < STW ? hn + ((size_t)l * BAT + mtile * 64 + (row)) * STW + (k)    \
         : (k) < STW + INW ? x + (size_t)(mtile * 64 + (row)) * INW + ((k) - STW) \
         : c + (size_t)(mtile * 64 + (row)) * CTXW + ((k) - STW - INW))
    #define UB_PTR(row, k)  (W + (size_t)(otile * 32 + (row)) * DW + (k))

    GEMM_PIPE_BODY(UA_PTR, UB_PTR, kbase)

    #undef UA_PTR
    #undef UB_PTR

    #pragma unroll
    for (int mi = 0; mi < 2; mi++) {
        const int r0 = mtile * 64 + wm * 32 + mi * 16;
        #pragma unroll
        for (int ni = 0; ni < 2; ni++) {
            const int o0 = otile * 32 + wn * 16 + ni * 8 + tg * 2;
            float2 v0 = { acc[mi][ni][0], acc[mi][ni][1] };
            float2 v1 = { acc[mi][ni][2], acc[mi][ni][3] };
            *(float2*)&g_uv_p[kh][which][l][r0 + g][o0]     = v0;
            *(float2*)&g_uv_p[kh][which][l][r0 + g + 8][o0] = v1;
        }
    }
}

// ---------------------------------------------------------------------------
// M update, fused across all 4 levels (each M element read exactly once).
// Sums u/v split-K partials + biases at staging.  Touch-once traffic ->
// evict-first streaming (__ldcs/__stcs).  R9-proven shape: grid (8,128),
// 256 threads, 8 iters/thread, regs ~48, occ ~51% (best measured: 45.5us).
// ---------------------------------------------------------------------------
__global__ __launch_bounds__(256)
void m_update(const float* __restrict__ M,
              const float* __restrict__ gamma_logits,
              const float* __restrict__ eta_logits,
              const float* __restrict__ u_b, const float* __restrict__ v_b,
              float* __restrict__ out)
{
    __shared__ float sv[4][256];
    __shared__ float su[4][32];
    __shared__ float sg[4], se[4];

    const int b  = blockIdx.y;
    const int ic = blockIdx.x;     // 0..7: 32-row chunk of i
    const int t  = threadIdx.x;

    for (int e = t; e < 1024; e += 256) {
        int l = e >> 8, j = e & 255;
        sv[l][j] = g_uv_p[0][1][l][b][j] + g_uv_p[1][1][l][b][j] + v_b[l * RW + j];
    }
    if (t < 128) {
        int l = t >> 5, i = t & 31;
        int r = ic * 32 + i;
        su[l][i] = g_uv_p[0][0][l][b][r] + g_uv_p[1][0][l][b][r] + u_b[l * RW + r];
    }
    if (t < 4) { sg[t] = sigmoidf_(gamma_logits[t]); se[t] = sigmoidf_(eta_logits[t]); }
    __syncthreads();

    float* mout = out + H_SIZE;

    #pragma unroll 1
    for (int it = 0; it < 8; it++) {
        const int p  = it * 256 + t;
        const int i  = p >> 6;              // 0..31
        const int j4 = (p & 63) << 2;       // 0..252
        const size_t base = ((size_t)b * RW + ic * 32 + i) * CW + j4;

        float4 m[4];
        #pragma unroll
        for (int l = 0; l < 4; l++)
            m[l] = __ldcs((const float4*)(M + (size_t)l * M_LVL_STRIDE + base));

        #pragma unroll
        for (int l = 0; l < 4; l++) {
            const int lu = (l == 0) ? 0 : l - 1;
            const int ld = (l == 3) ? 3 : l + 1;
            const float gg = sg[l];
            const float ue = se[l] * su[l][i];
            const float4 v = *(const float4*)&sv[l][j4];
            float4 o;
            o.x = (1.0f - gg) * m[l].x + 0.5f * gg * (m[lu].x + m[ld].x) + ue * v.x;
            o.y = (1.0f - gg) * m[l].y + 0.5f * gg * (m[lu].y + m[ld].y) + ue * v.y;
            o.z = (1.0f - gg) * m[l].z + 0.5f * gg * (m[lu].z + m[ld].z) + ue * v.z;
            o.w = (1.0f - gg) * m[l].w + 0.5f * gg * (m[lu].w + m[ld].w) + ue * v.w;
            __stcs((float4*)(mout + (size_t)l * M_LVL_STRIDE + base), o);
        }
    }
}

// ---------------------------------------------------------------------------
extern "C" void kernel_launch(void* const* d_in, const int* in_sizes, int n_in,
                              void* d_out, int out_size)
{
    const float* x       = (const float*)d_in[0];
    const float* c       = (const float*)d_in[1];
    const float* h       = (const float*)d_in[2];
    const float* M       = (const float*)d_in[3];
    const float* phi_w   = (const float*)d_in[4];
    const float* phi_b   = (const float*)d_in[5];
    const float* alpha_w = (const float*)d_in[6];
    const float* alpha_b = (const float*)d_in[7];
    const float* beta_w  = (const float*)d_in[8];
    const float* beta_b  = (const float*)d_in[9];
    const float* u_w     = (const float*)d_in[10];
    const float* u_b     = (const float*)d_in[11];
    const float* v_w     = (const float*)d_in[12];
    const float* v_b     = (const float*)d_in[13];
    const float* gamma_l = (const float*)d_in[14];
    const float* eta_l   = (const float*)d_in[15];

    float* out = (float*)d_out;

    // 1. gate GEMMs, split-K x2, truncation-mode tf32 -> g_gate_p
    gate_gemm<<<dim3(16, 4, 12), 128>>>(x, c, h, phi_w, alpha_w, beta_w);
    // 2. h_new (sums partials + biases) -> out[0:H_SIZE]
    hnew_kernel<<<H_SIZE4 / 256, 256>>>(h, phi_b, alpha_b, beta_b, out);
    // 3. u/v GEMMs, split-K x2 -> g_uv_p
    uv_gemm<<<dim3(8, 4, 8), 128>>>(out, x, c, u_w, v_w);
    // 4. fused 4-level M update (R9 shape; sums u/v partials) -> out[H_SIZE:]
    m_update<<<dim3(8, 128), 256>>>(M, gamma_l, eta_l, u_b, v_b, out);
}

// round 13
// speedup vs baseline: 1.0806x; 1.0806x over previous
#include <cuda_runtime.h>
#include <math.h>

#define LVL 4
#define BAT 128
#define INW 512
#define CTXW 512
#define STW 512
#define RW 256
#define CW 256
#define DW 1536
#define KC 32
#define KHALF 768                     /* K per split-K block */
#define NCH (KHALF/KC)                /* 24 chunks per half */
#define H_SIZE (LVL*BAT*STW)          /* 262144 */
#define H_SIZE4 (H_SIZE/4)            /* 65536 */
#define M_LVL_STRIDE (BAT*RW*CW)      /* 8388608 */

/* fused gate kernel dynamic smem: 3 stages x (A 64x36 + 3x B 32x36) floats */
#define GATE_SMEM_FLOATS (3 * (64 * 36 + 3 * 32 * 36))
#define GATE_SMEM_BYTES  (GATE_SMEM_FLOATS * 4)          /* 69120 */

// scratch (allocation-free rule: __device__ globals)
__device__ __align__(16) float g_gate_p[2][3][LVL][BAT][STW]; // split-K gate partials (6 MB)
__device__ __align__(16) float g_uv_p[2][2][LVL][BAT][RW];    // split-K u/v partials (2 MB)

__device__ __forceinline__ float sigmoidf_(float x) { return 1.0f / (1.0f + __expf(-x)); }

__device__ __forceinline__ void mma_tf32(float* d, unsigned a0, unsigned a1,
                                         unsigned a2, unsigned a3,
                                         unsigned b0, unsigned b1)
{
    asm volatile(
        "mma.sync.aligned.m16n8k8.row.col.f32.tf32.tf32.f32 "
        "{%0,%1,%2,%3}, {%4,%5,%6,%7}, {%8,%9}, {%0,%1,%2,%3};\n"
        : "+f"(d[0]), "+f"(d[1]), "+f"(d[2]), "+f"(d[3])
        : "r"(a0), "r"(a1), "r"(a2), "r"(a3), "r"(b0), "r"(b1));
}

__device__ __forceinline__ void cp16(void* dst, const void* src) {
    unsigned ds = (unsigned)__cvta_generic_to_shared(dst);
    asm volatile("cp.async.ca.shared.global [%0], [%1], 16;" :: "r"(ds), "l"(src));
}
__device__ __forceinline__ void cp_commit() { asm volatile("cp.async.commit_group;"); }
template<int N> __device__ __forceinline__ void cp_wait() {
    asm volatile("cp.async.wait_group %0;" :: "n"(N));
}

// ---------------------------------------------------------------------------
// FUSED gate GEMM, split-K x2: one block computes phi/alpha/beta partials for
// the same (mtile, otile, kh, l), sharing the A tile across all 3 gates.
// Tile M=64 x N=32 per gate, 128 threads (2x2 warps, warp tile 32x16).
// 3-stage cp.async pipeline (R10-proven ordering), truncation-mode tf32,
// stride-36 conflict-free smem rows.  Dynamic smem 67.5 KB -> 3 blocks/SM.
// grid: (otile=16, y=mtile*2+kh=4, z=l=4) = 256 blocks (single wave).
// ---------------------------------------------------------------------------
__global__ __launch_bounds__(128)
void gate_gemm(const float* __restrict__ x, const float* __restrict__ c,
               const float* __restrict__ h,
               const float* __restrict__ phi_w, const float* __restrict__ alpha_w,
               const float* __restrict__ beta_w)
{
    extern __shared__ float smem_dyn[];
    float (*As)[64][36]    = (float(*)[64][36])smem_dyn;                 // [3][64][36]
    float (*Bs)[3][32][36] = (float(*)[3][32][36])(smem_dyn + 3 * 64 * 36);

    const int l     = blockIdx.z;
    const int mtile = blockIdx.y >> 1;
    const int kh    = blockIdx.y & 1;
    const int otile = blockIdx.x;
    const int kbase = kh * KHALF;

    const int t = threadIdx.x;
    const int w = t >> 5, lane = t & 31;
    const int wm = w >> 1, wn = w & 1;
    const int g = lane >> 2, tg = lane & 3;

    const float* Wg[3] = { phi_w   + (size_t)l * STW * DW,
                           alpha_w + (size_t)l * STW * DW,
                           beta_w  + (size_t)l * STW * DW };

    float acc[3][2][2][4];
    #pragma unroll
    for (int ga = 0; ga < 3; ga++)
        #pragma unroll
        for (int mi = 0; mi < 2; mi++)
            #pragma unroll
            for (int ni = 0; ni < 2; ni++)
                #pragma unroll
                for (int r = 0; r < 4; r++) acc[ga][mi][ni][r] = 0.0f;

    // one KC=32 chunk into stage s: A 64x32 (4 f4/thr), B 3x32x32 (6 f4/thr)
    auto load_chunk = [&](int kt, int s) {
        #pragma unroll
        for (int i = 0; i < 4; i++) {
            const int idx = i * 128 + t;
            const int row = idx >> 3, ch = idx & 7;
            const int k = kt + ch * 4;
            const int b = mtile * 64 + row;
            const float* src;
            if (k < INW)              src = x + (size_t)b * INW + k;
            else if (k < INW + CTXW)  src = c + (size_t)b * CTXW + (k - INW);
            else                      src = h + ((size_t)l * BAT + b) * STW + (k - INW - CTXW);
            cp16(&As[s][row][ch * 4], src);
        }
        #pragma unroll
        for (int i = 0; i < 6; i++) {
            const int idx = i * 128 + t;          // 0..767
            const int ga  = idx >> 8;             // 0..2
            const int rem = idx & 255;
            const int row = rem >> 3, ch = rem & 7;
            cp16(&Bs[s][ga][row][ch * 4],
                 Wg[ga] + (size_t)(otile * 32 + row) * DW + kt + ch * 4);
        }
        cp_commit();
    };

    // 3-stage pipeline: prologue 2 groups; per iter wait<1> (wait<0> last —
    // wait<1> with 1 pending group would not wait: R6-class bug), barrier,
    // issue stage it+2 into slot (it+2)%3 (last read before this barrier).
    load_chunk(kbase, 0);
    load_chunk(kbase + KC, 1);
    for (int it = 0; it < NCH; ++it) {
        const int s = it % 3;
        if (it + 1 < NCH) cp_wait<1>(); else cp_wait<0>();
        __syncthreads();
        if (it + 2 < NCH) load_chunk(kbase + (it + 2) * KC, (it + 2) % 3);

        #pragma unroll
        for (int ks = 0; ks < 4; ks++) {
            const int k0 = ks * 8;
            unsigned a[2][4];
            #pragma unroll
            for (int mi = 0; mi < 2; mi++) {
                const int r0 = wm * 32 + mi * 16;
                a[mi][0] = __float_as_uint(As[s][r0 + g][k0 + tg]);
                a[mi][1] = __float_as_uint(As[s][r0 + g + 8][k0 + tg]);
                a[mi][2] = __float_as_uint(As[s][r0 + g][k0 + tg + 4]);
                a[mi][3] = __float_as_uint(As[s][r0 + g + 8][k0 + tg + 4]);
            }
            #pragma unroll
            for (int ga = 0; ga < 3; ga++) {
                unsigned bb[2][2];
                #pragma unroll
                for (int ni = 0; ni < 2; ni++) {
                    const int n0 = wn * 16 + ni * 8 + g;
                    bb[ni][0] = __float_as_uint(Bs[s][ga][n0][k0 + tg]);
                    bb[ni][1] = __float_as_uint(Bs[s][ga][n0][k0 + tg + 4]);
                }
                #pragma unroll
                for (int mi = 0; mi < 2; mi++)
                    #pragma unroll
                    for (int ni = 0; ni < 2; ni++)
                        mma_tf32(acc[ga][mi][ni], a[mi][0], a[mi][1], a[mi][2],
                                 a[mi][3], bb[ni][0], bb[ni][1]);
            }
        }
    }

    #pragma unroll
    for (int ga = 0; ga < 3; ga++)
        #pragma unroll
        for (int mi = 0; mi < 2; mi++) {
            const int r0 = mtile * 64 + wm * 32 + mi * 16;
            #pragma unroll
            for (int ni = 0; ni < 2; ni++) {
                const int o0 = otile * 32 + wn * 16 + ni * 8 + tg * 2;
                float2 v0 = { acc[ga][mi][ni][0], acc[ga][mi][ni][1] };
                float2 v1 = { acc[ga][mi][ni][2], acc[ga][mi][ni][3] };
                *(float2*)&g_gate_p[kh][ga][l][r0 + g][o0]     = v0;
                *(float2*)&g_gate_p[kh][ga][l][r0 + g + 8][o0] = v1;
            }
        }
}

// ---------------------------------------------------------------------------
// h_new = sigmoid(alpha)*tanh(phi) + sigmoid(beta)*h  -> d_out[0:H_SIZE]
// Sums the two split-K partials and adds biases.  float4 vectorized.
// ---------------------------------------------------------------------------
__global__ __launch_bounds__(256)
void hnew_kernel(const float* __restrict__ h,
                 const float* __restrict__ phi_b, const float* __restrict__ alpha_b,
                 const float* __restrict__ beta_b,
                 float* __restrict__ out)
{
    const int idx = blockIdx.x * blockDim.x + threadIdx.x;   // float4 index
    if (idx >= H_SIZE4) return;
    const float4* g0 = (const float4*)&g_gate_p[0][0][0][0][0];
    const float4* g1 = (const float4*)&g_gate_p[1][0][0][0][0];

    const int base = idx * 4;
    const int l = base >> 16;          // BAT*STW = 65536
    const int o = base & (STW - 1);
    const float4 pb = *(const float4*)(phi_b   + l * STW + o);
    const float4 ab = *(const float4*)(alpha_b + l * STW + o);
    const float4 bbv = *(const float4*)(beta_b + l * STW + o);

    float4 p0 = g0[idx],               p1 = g1[idx];
    float4 a0 = g0[H_SIZE4 + idx],     a1 = g1[H_SIZE4 + idx];
    float4 b0 = g0[2 * H_SIZE4 + idx], b1 = g1[2 * H_SIZE4 + idx];
    float4 hv = ((const float4*)h)[idx];

    float4 o4;
    o4.x = sigmoidf_(a0.x + a1.x + ab.x) * tanhf(p0.x + p1.x + pb.x) + sigmoidf_(b0.x + b1.x + bbv.x) * hv.x;
    o4.y = sigmoidf_(a0.y + a1.y + ab.y) * tanhf(p0.y + p1.y + pb.y) + sigmoidf_(b0.y + b1.y + bbv.y) * hv.y;
    o4.z = sigmoidf_(a0.z + a1.z + ab.z) * tanhf(p0.z + p1.z + pb.z) + sigmoidf_(b0.z + b1.z + bbv.z) * hv.z;
    o4.w = sigmoidf_(a0.w + a1.w + ab.w) * tanhf(p0.w + p1.w + pb.w) + sigmoidf_(b0.w + b1.w + bbv.w) * hv.w;
    ((float4*)out)[idx] = o4;
}

// ---------------------------------------------------------------------------
// u/v GEMM, split-K x2 (unfused; R11/R12-proven): partial dot, no bias.
// wv = h_new|x|c.  Static-smem 3-stage pipeline, tile M=64 x N=32.
// grid: (otile=8, y=mtile*2+kh=4, z=l*2+which=8) = 256 blocks.
// ---------------------------------------------------------------------------
__global__ __launch_bounds__(128)
void uv_gemm(const float* __restrict__ hn, const float* __restrict__ x,
             const float* __restrict__ c,
             const float* __restrict__ u_w, const float* __restrict__ v_w)
{
    __shared__ float As[3][64][36];
    __shared__ float Bs[3][32][36];

    const int zz = blockIdx.z;
    const int l = zz >> 1, which = zz & 1;
    const int mtile = blockIdx.y >> 1;
    const int kh    = blockIdx.y & 1;
    const int otile = blockIdx.x;
    const int kbase = kh * KHALF;

    const int t = threadIdx.x;
    const int w = t >> 5, lane = t & 31;
    const int wm = w >> 1, wn = w & 1;
    const int g = lane >> 2, tg = lane & 3;

    const float* W = (which ? v_w : u_w) + (size_t)l * RW * DW;

    float acc[2][2][4];
    #pragma unroll
    for (int mi = 0; mi < 2; mi++)
        #pragma unroll
        for (int ni = 0; ni < 2; ni++)
            #pragma unroll
            for (int r = 0; r < 4; r++) acc[mi][ni][r] = 0.0f;

    auto load_chunk = [&](int kt, int s) {
        #pragma unroll
        for (int i = 0; i < 4; i++) {
            const int idx = i * 128 + t;
            const int row = idx >> 3, ch = idx & 7;
            const int k = kt + ch * 4;
            const int b = mtile * 64 + row;
            const float* src;
            if (k < STW)              src = hn + ((size_t)l * BAT + b) * STW + k;
            else if (k < STW + INW)   src = x + (size_t)b * INW + (k - STW);
            else                      src = c + (size_t)b * CTXW + (k - STW - INW);
            cp16(&As[s][row][ch * 4], src);
        }
        #pragma unroll
        for (int i = 0; i < 2; i++) {
            const int idx = i * 128 + t;
            const int row = idx >> 3, ch = idx & 7;
            cp16(&Bs[s][row][ch * 4], W + (size_t)(otile * 32 + row) * DW + kt + ch * 4);
        }
        cp_commit();
    };

    load_chunk(kbase, 0);
    load_chunk(kbase + KC, 1);
    for (int it = 0; it < NCH; ++it) {
        const int s = it % 3;
        if (it + 1 < NCH) cp_wait<1>(); else cp_wait<0>();
        __syncthreads();
        if (it + 2 < NCH) load_chunk(kbase + (it + 2) * KC, (it + 2) % 3);

        #pragma unroll
        for (int ks = 0; ks < 4; ks++) {
            const int k0 = ks * 8;
            unsigned a[2][4];
            #pragma unroll
            for (int mi = 0; mi < 2; mi++) {
                const int r0 = wm * 32 + mi * 16;
                a[mi][0] = __float_as_uint(As[s][r0 + g][k0 + tg]);
                a[mi][1] = __float_as_uint(As[s][r0 + g + 8][k0 + tg]);
                a[mi][2] = __float_as_uint(As[s][r0 + g][k0 + tg + 4]);
                a[mi][3] = __float_as_uint(As[s][r0 + g + 8][k0 + tg + 4]);
            }
            unsigned bb[2][2];
            #pragma unroll
            for (int ni = 0; ni < 2; ni++) {
                const int n0 = wn * 16 + ni * 8 + g;
                bb[ni][0] = __float_as_uint(Bs[s][n0][k0 + tg]);
                bb[ni][1] = __float_as_uint(Bs[s][n0][k0 + tg + 4]);
            }
            #pragma unroll
            for (int mi = 0; mi < 2; mi++)
                #pragma unroll
                for (int ni = 0; ni < 2; ni++)
                    mma_tf32(acc[mi][ni], a[mi][0], a[mi][1], a[mi][2],
                             a[mi][3], bb[ni][0], bb[ni][1]);
        }
    }

    #pragma unroll
    for (int mi = 0; mi < 2; mi++) {
        const int r0 = mtile * 64 + wm * 32 + mi * 16;
        #pragma unroll
        for (int ni = 0; ni < 2; ni++) {
            const int o0 = otile * 32 + wn * 16 + ni * 8 + tg * 2;
            float2 v0 = { acc[mi][ni][0], acc[mi][ni][1] };
            float2 v1 = { acc[mi][ni][2], acc[mi][ni][3] };
            *(float2*)&g_uv_p[kh][which][l][r0 + g][o0]     = v0;
            *(float2*)&g_uv_p[kh][which][l][r0 + g + 8][o0] = v1;
        }
    }
}

// ---------------------------------------------------------------------------
// M update, fused across all 4 levels (each M element read exactly once).
// Sums u/v split-K partials + biases at staging.  Touch-once traffic ->
// evict-first streaming (__ldcs/__stcs).  R9-proven shape: grid (8,128).
// ---------------------------------------------------------------------------
__global__ __launch_bounds__(256)
void m_update(const float* __restrict__ M,
              const float* __restrict__ gamma_logits,
              const float* __restrict__ eta_logits,
              const float* __restrict__ u_b, const float* __restrict__ v_b,
              float* __restrict__ out)
{
    __shared__ float sv[4][256];
    __shared__ float su[4][32];
    __shared__ float sg[4], se[4];

    const int b  = blockIdx.y;
    const int ic = blockIdx.x;     // 0..7: 32-row chunk of i
    const int t  = threadIdx.x;

    for (int e = t; e < 1024; e += 256) {
        int l = e >> 8, j = e & 255;
        sv[l][j] = g_uv_p[0][1][l][b][j] + g_uv_p[1][1][l][b][j] + v_b[l * RW + j];
    }
    if (t < 128) {
        int l = t >> 5, i = t & 31;
        int r = ic * 32 + i;
        su[l][i] = g_uv_p[0][0][l][b][r] + g_uv_p[1][0][l][b][r] + u_b[l * RW + r];
    }
    if (t < 4) { sg[t] = sigmoidf_(gamma_logits[t]); se[t] = sigmoidf_(eta_logits[t]); }
    __syncthreads();

    float* mout = out + H_SIZE;

    #pragma unroll 1
    for (int it = 0; it < 8; it++) {
        const int p  = it * 256 + t;
        const int i  = p >> 6;              // 0..31
        const int j4 = (p & 63) << 2;       // 0..252
        const size_t base = ((size_t)b * RW + ic * 32 + i) * CW + j4;

        float4 m[4];
        #pragma unroll
        for (int l = 0; l < 4; l++)
            m[l] = __ldcs((const float4*)(M + (size_t)l * M_LVL_STRIDE + base));

        #pragma unroll
        for (int l = 0; l < 4; l++) {
            const int lu = (l == 0) ? 0 : l - 1;
            const int ld = (l == 3) ? 3 : l + 1;
            const float gg = sg[l];
            const float ue = se[l] * su[l][i];
            const float4 v = *(const float4*)&sv[l][j4];
            float4 o;
            o.x = (1.0f - gg) * m[l].x + 0.5f * gg * (m[lu].x + m[ld].x) + ue * v.x;
            o.y = (1.0f - gg) * m[l].y + 0.5f * gg * (m[lu].y + m[ld].y) + ue * v.y;
            o.z = (1.0f - gg) * m[l].z + 0.5f * gg * (m[lu].z + m[ld].z) + ue * v.z;
            o.w = (1.0f - gg) * m[l].w + 0.5f * gg * (m[lu].w + m[ld].w) + ue * v.w;
            __stcs((float4*)(mout + (size_t)l * M_LVL_STRIDE + base), o);
        }
    }
}

// ---------------------------------------------------------------------------
extern "C" void kernel_launch(void* const* d_in, const int* in_sizes, int n_in,
                              void* d_out, int out_size)
{
    const float* x       = (const float*)d_in[0];
    const float* c       = (const float*)d_in[1];
    const float* h       = (const float*)d_in[2];
    const float* M       = (const float*)d_in[3];
    const float* phi_w   = (const float*)d_in[4];
    const float* phi_b   = (const float*)d_in[5];
    const float* alpha_w = (const float*)d_in[6];
    const float* alpha_b = (const float*)d_in[7];
    const float* beta_w  = (const float*)d_in[8];
    const float* beta_b  = (const float*)d_in[9];
    const float* u_w     = (const float*)d_in[10];
    const float* u_b     = (const float*)d_in[11];
    const float* v_w     = (const float*)d_in[12];
    const float* v_b     = (const float*)d_in[13];
    const float* gamma_l = (const float*)d_in[14];
    const float* eta_l   = (const float*)d_in[15];

    float* out = (float*)d_out;

    // idempotent; first call happens on the uncaptured correctness run
    cudaFuncSetAttribute(gate_gemm, cudaFuncAttributeMaxDynamicSharedMemorySize,
                         GATE_SMEM_BYTES);

    // 1. FUSED gate GEMMs (3 gates share A tile), split-K x2 -> g_gate_p
    gate_gemm<<<dim3(16, 4, 4), 128, GATE_SMEM_BYTES>>>(x, c, h,
                                                        phi_w, alpha_w, beta_w);
    // 2. h_new (sums partials + biases) -> out[0:H_SIZE]
    hnew_kernel<<<H_SIZE4 / 256, 256>>>(h, phi_b, alpha_b, beta_b, out);
    // 3. u/v GEMMs, split-K x2 -> g_uv_p
    uv_gemm<<<dim3(8, 4, 8), 128>>>(out, x, c, u_w, v_w);
    // 4. fused 4-level M update (R9 shape; sums u/v partials) -> out[H_SIZE:]
    m_update<<<dim3(8, 128), 256>>>(M, gamma_l, eta_l, u_b, v_b, out);
}

// round 14
// speedup vs baseline: 1.1304x; 1.0462x over previous
#include <cuda_runtime.h>
#include <math.h>

#define LVL 4
#define BAT 128
#define INW 512
#define CTXW 512
#define STW 512
#define RW 256
#define CW 256
#define DW 1536
#define KC 32
#define KHALF 768                     /* K per split-K block */
#define NCH (KHALF/KC)                /* 24 chunks per half */
#define H_SIZE (LVL*BAT*STW)          /* 262144 */
#define H_SIZE4 (H_SIZE/4)            /* 65536 */
#define M_LVL_STRIDE (BAT*RW*CW)      /* 8388608 */

/* fused gate kernel dynamic smem: 3 stages x (A 64x36 + 3x B 32x36) floats */
#define GATE_SMEM_BYTES  (3 * (64 * 36 + 3 * 32 * 36) * 4)   /* 69120 */
/* fused uv kernel dynamic smem: 3 stages x (A 64x36 + 2x B 32x36) floats */
#define UV_SMEM_BYTES    (3 * (64 * 36 + 2 * 32 * 36) * 4)   /* 55296 */
/* m_update staging: 4 stages x 4 levels x 256 float4 */
#define MUPD_SMEM_BYTES  (4 * 4 * 256 * 16)                  /* 65536 */

// scratch (allocation-free rule: __device__ globals)
__device__ __align__(16) float g_gate_p[2][3][LVL][BAT][STW]; // split-K gate partials (6 MB)
__device__ __align__(16) float g_uv_p[2][2][LVL][BAT][RW];    // split-K u/v partials (2 MB)

__device__ __forceinline__ float sigmoidf_(float x) { return 1.0f / (1.0f + __expf(-x)); }

__device__ __forceinline__ void mma_tf32(float* d, unsigned a0, unsigned a1,
                                         unsigned a2, unsigned a3,
                                         unsigned b0, unsigned b1)
{
    asm volatile(
        "mma.sync.aligned.m16n8k8.row.col.f32.tf32.tf32.f32 "
        "{%0,%1,%2,%3}, {%4,%5,%6,%7}, {%8,%9}, {%0,%1,%2,%3};\n"
        : "+f"(d[0]), "+f"(d[1]), "+f"(d[2]), "+f"(d[3])
        : "r"(a0), "r"(a1), "r"(a2), "r"(a3), "r"(b0), "r"(b1));
}

__device__ __forceinline__ void cp16(void* dst, const void* src) {
    unsigned ds = (unsigned)__cvta_generic_to_shared(dst);
    asm volatile("cp.async.ca.shared.global [%0], [%1], 16;" :: "r"(ds), "l"(src));
}
// L1-bypassing variant for touch-once streams
__device__ __forceinline__ void cp16cg(void* dst, const void* src) {
    unsigned ds = (unsigned)__cvta_generic_to_shared(dst);
    asm volatile("cp.async.cg.shared.global [%0], [%1], 16;" :: "r"(ds), "l"(src));
}
__device__ __forceinline__ void cp_commit() { asm volatile("cp.async.commit_group;"); }
template<int N> __device__ __forceinline__ void cp_wait() {
    asm volatile("cp.async.wait_group %0;" :: "n"(N));
}

// ---------------------------------------------------------------------------
// FUSED gate GEMM, split-K x2 (R13-proven): one block computes phi/alpha/beta
// partials for the same (mtile, otile, kh, l), sharing the A tile.
// Tile M=64 x N=32 per gate, 128 threads, 3-stage cp.async pipeline,
// truncation-mode tf32, stride-36 conflict-free smem.
// grid: (otile=16, y=mtile*2+kh=4, z=l=4) = 256 blocks.
// ---------------------------------------------------------------------------
__global__ __launch_bounds__(128)
void gate_gemm(const float* __restrict__ x, const float* __restrict__ c,
               const float* __restrict__ h,
               const float* __restrict__ phi_w, const float* __restrict__ alpha_w,
               const float* __restrict__ beta_w)
{
    extern __shared__ float smem_dyn[];
    float (*As)[64][36]    = (float(*)[64][36])smem_dyn;                 // [3][64][36]
    float (*Bs)[3][32][36] = (float(*)[3][32][36])(smem_dyn + 3 * 64 * 36);

    const int l     = blockIdx.z;
    const int mtile = blockIdx.y >> 1;
    const int kh    = blockIdx.y & 1;
    const int otile = blockIdx.x;
    const int kbase = kh * KHALF;

    const int t = threadIdx.x;
    const int w = t >> 5, lane = t & 31;
    const int wm = w >> 1, wn = w & 1;
    const int g = lane >> 2, tg = lane & 3;

    const float* Wg[3] = { phi_w   + (size_t)l * STW * DW,
                           alpha_w + (size_t)l * STW * DW,
                           beta_w  + (size_t)l * STW * DW };

    float acc[3][2][2][4];
    #pragma unroll
    for (int ga = 0; ga < 3; ga++)
        #pragma unroll
        for (int mi = 0; mi < 2; mi++)
            #pragma unroll
            for (int ni = 0; ni < 2; ni++)
                #pragma unroll
                for (int r = 0; r < 4; r++) acc[ga][mi][ni][r] = 0.0f;

    auto load_chunk = [&](int kt, int s) {
        #pragma unroll
        for (int i = 0; i < 4; i++) {
            const int idx = i * 128 + t;
            const int row = idx >> 3, ch = idx & 7;
            const int k = kt + ch * 4;
            const int b = mtile * 64 + row;
            const float* src;
            if (k < INW)              src = x + (size_t)b * INW + k;
            else if (k < INW + CTXW)  src = c + (size_t)b * CTXW + (k - INW);
            else                      src = h + ((size_t)l * BAT + b) * STW + (k - INW - CTXW);
            cp16(&As[s][row][ch * 4], src);
        }
        #pragma unroll
        for (int i = 0; i < 6; i++) {
            const int idx = i * 128 + t;          // 0..767
            const int ga  = idx >> 8;             // 0..2
            const int rem = idx & 255;
            const int row = rem >> 3, ch = rem & 7;
            cp16(&Bs[s][ga][row][ch * 4],
                 Wg[ga] + (size_t)(otile * 32 + row) * DW + kt + ch * 4);
        }
        cp_commit();
    };

    // 3-stage pipeline (wait<1> with only 1 pending group would not wait —
    // the R6-class bug — hence the wait<0> on the last iteration).
    load_chunk(kbase, 0);
    load_chunk(kbase + KC, 1);
    for (int it = 0; it < NCH; ++it) {
        const int s = it % 3;
        if (it + 1 < NCH) cp_wait<1>(); else cp_wait<0>();
        __syncthreads();
        if (it + 2 < NCH) load_chunk(kbase + (it + 2) * KC, (it + 2) % 3);

        #pragma unroll
        for (int ks = 0; ks < 4; ks++) {
            const int k0 = ks * 8;
            unsigned a[2][4];
            #pragma unroll
            for (int mi = 0; mi < 2; mi++) {
                const int r0 = wm * 32 + mi * 16;
                a[mi][0] = __float_as_uint(As[s][r0 + g][k0 + tg]);
                a[mi][1] = __float_as_uint(As[s][r0 + g + 8][k0 + tg]);
                a[mi][2] = __float_as_uint(As[s][r0 + g][k0 + tg + 4]);
                a[mi][3] = __float_as_uint(As[s][r0 + g + 8][k0 + tg + 4]);
            }
            #pragma unroll
            for (int ga = 0; ga < 3; ga++) {
                unsigned bb[2][2];
                #pragma unroll
                for (int ni = 0; ni < 2; ni++) {
                    const int n0 = wn * 16 + ni * 8 + g;
                    bb[ni][0] = __float_as_uint(Bs[s][ga][n0][k0 + tg]);
                    bb[ni][1] = __float_as_uint(Bs[s][ga][n0][k0 + tg + 4]);
                }
                #pragma unroll
                for (int mi = 0; mi < 2; mi++)
                    #pragma unroll
                    for (int ni = 0; ni < 2; ni++)
                        mma_tf32(acc[ga][mi][ni], a[mi][0], a[mi][1], a[mi][2],
                                 a[mi][3], bb[ni][0], bb[ni][1]);
            }
        }
    }

    #pragma unroll
    for (int ga = 0; ga < 3; ga++)
        #pragma unroll
        for (int mi = 0; mi < 2; mi++) {
            const int r0 = mtile * 64 + wm * 32 + mi * 16;
            #pragma unroll
            for (int ni = 0; ni < 2; ni++) {
                const int o0 = otile * 32 + wn * 16 + ni * 8 + tg * 2;
                float2 v0 = { acc[ga][mi][ni][0], acc[ga][mi][ni][1] };
                float2 v1 = { acc[ga][mi][ni][2], acc[ga][mi][ni][3] };
                *(float2*)&g_gate_p[kh][ga][l][r0 + g][o0]     = v0;
                *(float2*)&g_gate_p[kh][ga][l][r0 + g + 8][o0] = v1;
            }
        }
}

// ---------------------------------------------------------------------------
// h_new = sigmoid(alpha)*tanh(phi) + sigmoid(beta)*h  -> d_out[0:H_SIZE]
// Sums the two split-K partials and adds biases.  float4 vectorized.
// ---------------------------------------------------------------------------
__global__ __launch_bounds__(256)
void hnew_kernel(const float* __restrict__ h,
                 const float* __restrict__ phi_b, const float* __restrict__ alpha_b,
                 const float* __restrict__ beta_b,
                 float* __restrict__ out)
{
    const int idx = blockIdx.x * blockDim.x + threadIdx.x;   // float4 index
    if (idx >= H_SIZE4) return;
    const float4* g0 = (const float4*)&g_gate_p[0][0][0][0][0];
    const float4* g1 = (const float4*)&g_gate_p[1][0][0][0][0];

    const int base = idx * 4;
    const int l = base >> 16;          // BAT*STW = 65536
    const int o = base & (STW - 1);
    const float4 pb = *(const float4*)(phi_b   + l * STW + o);
    const float4 ab = *(const float4*)(alpha_b + l * STW + o);
    const float4 bbv = *(const float4*)(beta_b + l * STW + o);

    float4 p0 = g0[idx],               p1 = g1[idx];
    float4 a0 = g0[H_SIZE4 + idx],     a1 = g1[H_SIZE4 + idx];
    float4 b0 = g0[2 * H_SIZE4 + idx], b1 = g1[2 * H_SIZE4 + idx];
    float4 hv = ((const float4*)h)[idx];

    float4 o4;
    o4.x = sigmoidf_(a0.x + a1.x + ab.x) * tanhf(p0.x + p1.x + pb.x) + sigmoidf_(b0.x + b1.x + bbv.x) * hv.x;
    o4.y = sigmoidf_(a0.y + a1.y + ab.y) * tanhf(p0.y + p1.y + pb.y) + sigmoidf_(b0.y + b1.y + bbv.y) * hv.y;
    o4.z = sigmoidf_(a0.z + a1.z + ab.z) * tanhf(p0.z + p1.z + pb.z) + sigmoidf_(b0.z + b1.z + bbv.z) * hv.z;
    o4.w = sigmoidf_(a0.w + a1.w + ab.w) * tanhf(p0.w + p1.w + pb.w) + sigmoidf_(b0.w + b1.w + bbv.w) * hv.w;
    ((float4*)out)[idx] = o4;
}

// ---------------------------------------------------------------------------
// FUSED u/v GEMM, split-K x2: one block computes BOTH u and v partials for
// the same (mtile, otile, kh, l), sharing the A tile (R13-fusion mechanism:
// halves blocks 256 -> 128 = single wave, 1 block/SM).  wv = h_new|x|c.
// grid: (otile=8, y=mtile*2+kh=4, z=l=4) = 128 blocks.
// ---------------------------------------------------------------------------
__global__ __launch_bounds__(128)
void uv_gemm(const float* __restrict__ hn, const float* __restrict__ x,
             const float* __restrict__ c,
             const float* __restrict__ u_w, const float* __restrict__ v_w)
{
    extern __shared__ float smem_dyn[];
    float (*As)[64][36]    = (float(*)[64][36])smem_dyn;                 // [3][64][36]
    float (*Bs)[2][32][36] = (float(*)[2][32][36])(smem_dyn + 3 * 64 * 36);

    const int l     = blockIdx.z;
    const int mtile = blockIdx.y >> 1;
    const int kh    = blockIdx.y & 1;
    const int otile = blockIdx.x;
    const int kbase = kh * KHALF;

    const int t = threadIdx.x;
    const int w = t >> 5, lane = t & 31;
    const int wm = w >> 1, wn = w & 1;
    const int g = lane >> 2, tg = lane & 3;

    const float* Wuv[2] = { u_w + (size_t)l * RW * DW,
                            v_w + (size_t)l * RW * DW };

    float acc[2][2][2][4];
    #pragma unroll
    for (int wv = 0; wv < 2; wv++)
        #pragma unroll
        for (int mi = 0; mi < 2; mi++)
            #pragma unroll
            for (int ni = 0; ni < 2; ni++)
                #pragma unroll
                for (int r = 0; r < 4; r++) acc[wv][mi][ni][r] = 0.0f;

    auto load_chunk = [&](int kt, int s) {
        #pragma unroll
        for (int i = 0; i < 4; i++) {
            const int idx = i * 128 + t;
            const int row = idx >> 3, ch = idx & 7;
            const int k = kt + ch * 4;
            const int b = mtile * 64 + row;
            const float* src;
            if (k < STW)              src = hn + ((size_t)l * BAT + b) * STW + k;
            else if (k < STW + INW)   src = x + (size_t)b * INW + (k - STW);
            else                      src = c + (size_t)b * CTXW + (k - STW - INW);
            cp16(&As[s][row][ch * 4], src);
        }
        #pragma unroll
        for (int i = 0; i < 4; i++) {
            const int idx = i * 128 + t;          // 0..511
            const int wv  = idx >> 8;             // 0..1
            const int rem = idx & 255;
            const int row = rem >> 3, ch = rem & 7;
            cp16(&Bs[s][wv][row][ch * 4],
                 Wuv[wv] + (size_t)(otile * 32 + row) * DW + kt + ch * 4);
        }
        cp_commit();
    };

    load_chunk(kbase, 0);
    load_chunk(kbase + KC, 1);
    for (int it = 0; it < NCH; ++it) {
        const int s = it % 3;
        if (it + 1 < NCH) cp_wait<1>(); else cp_wait<0>();
        __syncthreads();
        if (it + 2 < NCH) load_chunk(kbase + (it + 2) * KC, (it + 2) % 3);

        #pragma unroll
        for (int ks = 0; ks < 4; ks++) {
            const int k0 = ks * 8;
            unsigned a[2][4];
            #pragma unroll
            for (int mi = 0; mi < 2; mi++) {
                const int r0 = wm * 32 + mi * 16;
                a[mi][0] = __float_as_uint(As[s][r0 + g][k0 + tg]);
                a[mi][1] = __float_as_uint(As[s][r0 + g + 8][k0 + tg]);
                a[mi][2] = __float_as_uint(As[s][r0 + g][k0 + tg + 4]);
                a[mi][3] = __float_as_uint(As[s][r0 + g + 8][k0 + tg + 4]);
            }
            #pragma unroll
            for (int wv = 0; wv < 2; wv++) {
                unsigned bb[2][2];
                #pragma unroll
                for (int ni = 0; ni < 2; ni++) {
                    const int n0 = wn * 16 + ni * 8 + g;
                    bb[ni][0] = __float_as_uint(Bs[s][wv][n0][k0 + tg]);
                    bb[ni][1] = __float_as_uint(Bs[s][wv][n0][k0 + tg + 4]);
                }
                #pragma unroll
                for (int mi = 0; mi < 2; mi++)
                    #pragma unroll
                    for (int ni = 0; ni < 2; ni++)
                        mma_tf32(acc[wv][mi][ni], a[mi][0], a[mi][1], a[mi][2],
                                 a[mi][3], bb[ni][0], bb[ni][1]);
            }
        }
    }

    #pragma unroll
    for (int wv = 0; wv < 2; wv++)
        #pragma unroll
        for (int mi = 0; mi < 2; mi++) {
            const int r0 = mtile * 64 + wm * 32 + mi * 16;
            #pragma unroll
            for (int ni = 0; ni < 2; ni++) {
                const int o0 = otile * 32 + wn * 16 + ni * 8 + tg * 2;
                float2 v0 = { acc[wv][mi][ni][0], acc[wv][mi][ni][1] };
                float2 v1 = { acc[wv][mi][ni][2], acc[wv][mi][ni][3] };
                *(float2*)&g_uv_p[kh][wv][l][r0 + g][o0]     = v0;
                *(float2*)&g_uv_p[kh][wv][l][r0 + g + 8][o0] = v1;
            }
        }
}

// ---------------------------------------------------------------------------
// M update, fused across all 4 levels (each M element read exactly once).
// cp.async(.cg)-staged M loads: 4-stage, 3-ahead pipeline through dynamic
// smem -> 12 outstanding 16B loads/thread at ~40 regs (R10's register
// double-buffer hit the reg/occupancy wall; this doesn't).  NO barrier in the
// loop: each thread reads back only the smem words it staged itself, and the
// staged values are consumed (data dependency) before the slot is re-issued.
// Stores remain direct __stcs.  grid: (ichunk=8, b=128), 256 threads.
// ---------------------------------------------------------------------------
__global__ __launch_bounds__(256)
void m_update(const float* __restrict__ M,
              const float* __restrict__ gamma_logits,
              const float* __restrict__ eta_logits,
              const float* __restrict__ u_b, const float* __restrict__ v_b,
              float* __restrict__ out)
{
    extern __shared__ float4 mstage[];   // [4 stages][4 levels][256 threads]
    __shared__ float sv[4][256];
    __shared__ float su[4][32];
    __shared__ float sg[4], se[4];

    const int b  = blockIdx.y;
    const int ic = blockIdx.x;     // 0..7: 32-row chunk of i
    const int t  = threadIdx.x;

    for (int e = t; e < 1024; e += 256) {
        int l = e >> 8, j = e & 255;
        sv[l][j] = g_uv_p[0][1][l][b][j] + g_uv_p[1][1][l][b][j] + v_b[l * RW + j];
    }
    if (t < 128) {
        int l = t >> 5, i = t & 31;
        int r = ic * 32 + i;
        su[l][i] = g_uv_p[0][0][l][b][r] + g_uv_p[1][0][l][b][r] + u_b[l * RW + r];
    }
    if (t < 4) { sg[t] = sigmoidf_(gamma_logits[t]); se[t] = sigmoidf_(eta_logits[t]); }
    __syncthreads();

    float* mout = out + H_SIZE;

    auto issue_stage = [&](int it) {
        const int s  = it & 3;
        const int p  = it * 256 + t;
        const size_t base = ((size_t)b * RW + ic * 32 + (p >> 6)) * CW + ((p & 63) << 2);
        #pragma unroll
        for (int l = 0; l < 4; l++)
            cp16cg(&mstage[(s * 4 + l) * 256 + t],
                   M + (size_t)l * M_LVL_STRIDE + base);
        cp_commit();
    };

    issue_stage(0); issue_stage(1); issue_stage(2);

    #pragma unroll 1
    for (int it = 0; it < 8; it++) {
        if (it + 3 < 8) issue_stage(it + 3);
        // drain so stage `it` is complete (tail shrinks the pending count)
        if (it < 5)       cp_wait<3>();
        else if (it == 5) cp_wait<2>();
        else if (it == 6) cp_wait<1>();
        else              cp_wait<0>();

        const int s  = it & 3;
        const int p  = it * 256 + t;
        const int i  = p >> 6;
        const int j4 = (p & 63) << 2;
        const size_t base = ((size_t)b * RW + ic * 32 + i) * CW + j4;

        float4 m[4];
        #pragma unroll
        for (int l = 0; l < 4; l++)
            m[l] = mstage[(s * 4 + l) * 256 + t];

        #pragma unroll
        for (int l = 0; l < 4; l++) {
            const int lu = (l == 0) ? 0 : l - 1;
            const int ld = (l == 3) ? 3 : l + 1;
            const float gg = sg[l];
            const float ue = se[l] * su[l][i];
            const float4 v = *(const float4*)&sv[l][j4];
            float4 o;
            o.x = (1.0f - gg) * m[l].x + 0.5f * gg * (m[lu].x + m[ld].x) + ue * v.x;
            o.y = (1.0f - gg) * m[l].y + 0.5f * gg * (m[lu].y + m[ld].y) + ue * v.y;
            o.z = (1.0f - gg) * m[l].z + 0.5f * gg * (m[lu].z + m[ld].z) + ue * v.z;
            o.w = (1.0f - gg) * m[l].w + 0.5f * gg * (m[lu].w + m[ld].w) + ue * v.w;
            __stcs((float4*)(mout + (size_t)l * M_LVL_STRIDE + base), o);
        }
    }
}

// ---------------------------------------------------------------------------
extern "C" void kernel_launch(void* const* d_in, const int* in_sizes, int n_in,
                              void* d_out, int out_size)
{
    const float* x       = (const float*)d_in[0];
    const float* c       = (const float*)d_in[1];
    const float* h       = (const float*)d_in[2];
    const float* M       = (const float*)d_in[3];
    const float* phi_w   = (const float*)d_in[4];
    const float* phi_b   = (const float*)d_in[5];
    const float* alpha_w = (const float*)d_in[6];
    const float* alpha_b = (const float*)d_in[7];
    const float* beta_w  = (const float*)d_in[8];
    const float* beta_b  = (const float*)d_in[9];
    const float* u_w     = (const float*)d_in[10];
    const float* u_b     = (const float*)d_in[11];
    const float* v_w     = (const float*)d_in[12];
    const float* v_b     = (const float*)d_in[13];
    const float* gamma_l = (const float*)d_in[14];
    const float* eta_l   = (const float*)d_in[15];

    float* out = (float*)d_out;

    // idempotent; first calls happen on the uncaptured correctness run
    cudaFuncSetAttribute(gate_gemm, cudaFuncAttributeMaxDynamicSharedMemorySize,
                         GATE_SMEM_BYTES);
    cudaFuncSetAttribute(uv_gemm, cudaFuncAttributeMaxDynamicSharedMemorySize,
                         UV_SMEM_BYTES);
    cudaFuncSetAttribute(m_update, cudaFuncAttributeMaxDynamicSharedMemorySize,
                         MUPD_SMEM_BYTES);

    // 1. FUSED gate GEMMs (3 gates share A tile), split-K x2 -> g_gate_p
    gate_gemm<<<dim3(16, 4, 4), 128, GATE_SMEM_BYTES>>>(x, c, h,
                                                        phi_w, alpha_w, beta_w);
    // 2. h_new (sums partials + biases) -> out[0:H_SIZE]
    hnew_kernel<<<H_SIZE4 / 256, 256>>>(h, phi_b, alpha_b, beta_b, out);
    // 3. FUSED u/v GEMMs (u+v share A tile), split-K x2 -> g_uv_p
    uv_gemm<<<dim3(8, 4, 4), 128, UV_SMEM_BYTES>>>(out, x, c, u_w, v_w);
    // 4. fused 4-level M update (cp.async-staged loads) -> out[H_SIZE:]
    m_update<<<dim3(8, 128), 256, MUPD_SMEM_BYTES>>>(M, gamma_l, eta_l,
                                                     u_b, v_b, out);
}